// round 7
// baseline (speedup 1.0000x reference)
#include <cuda_runtime.h>
#include <cuda_fp16.h>
#include <cstdint>

// Problem constants: B=4, N=1024, C=16, H=W=128
#define BB 4
#define NN 1024
#define CC 16
#define HW 128

// f16 separable factors: ev [b][gv][n], euT [b][gu][n] (gu-major!)
__device__ unsigned short g_ev [BB * HW * NN];
__device__ unsigned short g_euT[BB * HW * NN];

__device__ __forceinline__ float ex2f(float x) {
    float y;
    asm("ex2.approx.ftz.f32 %0, %1;" : "=f"(y) : "f"(x));
    return y;
}

__device__ __forceinline__ uint32_t hmul2(uint32_t a, uint32_t b) {
    uint32_t d;
    asm("mul.rn.f16x2 %0, %1, %2;" : "=r"(d) : "r"(a), "r"(b));
    return d;
}

__device__ __forceinline__ void mma16816(float* d, const uint32_t* a,
                                         const uint32_t* b) {
    asm volatile(
        "mma.sync.aligned.m16n8k16.row.col.f32.f16.f16.f32 "
        "{%0,%1,%2,%3}, {%4,%5,%6,%7}, {%8,%9}, {%0,%1,%2,%3};"
        : "+f"(d[0]), "+f"(d[1]), "+f"(d[2]), "+f"(d[3])
        : "r"(a[0]), "r"(a[1]), "r"(a[2]), "r"(a[3]), "r"(b[0]), "r"(b[1]));
}

// ---------------------------------------------------------------------------
// Kernel A: project points, write f16 separable factors.
// grid = B*N/32 = 128 blocks, 128 threads; block = 32 points of one batch.
// ---------------------------------------------------------------------------
__global__ void __launch_bounds__(128) proj_kernel(
    const float* __restrict__ Kc,
    const float* __restrict__ RT,
    const float* __restrict__ pts3d,
    const float* __restrict__ scale)
{
    const int b  = blockIdx.x >> 5;
    const int n0 = (blockIdx.x & 31) << 5;
    const int tid = threadIdx.x;

    __shared__ float su[32], sv[32], sinv[32], smask[32];

    if (tid < 32) {
        const int n = n0 + tid;
        const float* rt = RT + b * 12;
        const float* p  = pts3d + (b * NN + n) * 3;
        float p0 = p[0], p1 = p[1], p2 = p[2];
        float l0 = rt[0] * p0 + rt[1] * p1 + rt[2]  * p2 + rt[3];
        float l1 = rt[4] * p0 + rt[5] * p1 + rt[6]  * p2 + rt[7];
        float l2 = rt[8] * p0 + rt[9] * p1 + rt[10] * p2 + rt[11];
        float x = Kc[0] * l0 + Kc[1] * l1 + Kc[2] * l2;
        float y = Kc[3] * l0 + Kc[4] * l1 + Kc[5] * l2;
        float z = Kc[6] * l0 + Kc[7] * l1 + Kc[8] * l2;
        float mask = (z > 0.1f) ? 1.0f : 0.0f;
        float zc = fmaxf(z, 0.1f);
        float sig = Kc[0] * 0.03125f;            // sigma = K[0,0]/32
        float inv = 1.0f / (scale[b * NN + n] * sig * sig);
        su[tid]   = x / zc;
        sv[tid]   = y / zc;
        sinv[tid] = -1.4426950408889634f * inv;  // fold -log2(e)
        smask[tid] = mask;
    }
    __syncthreads();

    const int warp = tid >> 5;
    const int lane = tid & 31;

    // ev[b][gv][n0+lane] (f16): thread owns point `lane`, warp covers 32 gv.
    {
        const float v  = sv[lane];
        const float ni = sinv[lane];
        unsigned short* dst = g_ev + (size_t)(b * HW) * NN + n0 + lane;
        #pragma unroll 8
        for (int j = 0; j < 32; j++) {
            const int gv = warp * 32 + j;
            float d = v - (float)gv;
            __half h = __float2half(ex2f(d * d * ni));
            dst[(size_t)gv * NN] = __half_as_ushort(h);
        }
    }
    // euT[b][gu][n0+i] (f16, gu-major): thread owns point i = lane, warp-group
    // covers 32 gu rows; stores coalesced along n. Mask folded here.
    {
        const int i = lane;
        const float u  = su[i];
        const float ni = sinv[i];
        const float m  = smask[i];
        unsigned short* dst = g_euT + (size_t)(b * HW) * NN + n0 + i;
        #pragma unroll 8
        for (int j = 0; j < 32; j++) {
            const int gu = warp * 32 + j;
            float d = u - (float)gu;
            __half h = __float2half(ex2f(d * d * ni) * m);
            dst[(size_t)gu * NN] = __half_as_ushort(h);
        }
    }
}

// ---------------------------------------------------------------------------
// Kernel B: register-direct HMMA GEMM, no W smem, no mainloop barriers.
// grid = 128 CTAs = (b, 4 gv rows), 512 threads = 16 warps.
// Warp (mt = wid&7, rp = wid>>3): D[gu in mt*16..+16][c 0..16] for rows
// gv0 + rp*2 + {0,1}. A-fragments built in registers:
//   a(gu, n-pair) = f16x2( ev[r][n-pair] * euT[gu][n-pair] )
// eu from gmem (L2-resident, prefetched 1 chunk ahead); ev + featT from smem.
// ---------------------------------------------------------------------------
__global__ void __launch_bounds__(512, 1) accum_kernel(
    const float* __restrict__ feat,
    float* __restrict__ out)
{
    __shared__ __align__(16) unsigned short sft[16][1032];  // featT [c][k], padded
    __shared__ __align__(16) unsigned short sev[4][1024];   // ev [r][n]

    const int b   = blockIdx.x >> 5;
    const int gv0 = (blockIdx.x & 31) << 2;
    const int t    = threadIdx.x;
    const int wid  = t >> 5;
    const int lane = t & 31;

    // ---- stage featT (f32 -> f16) ----
    {
        const int c  = t & 15;
        const int nv = t >> 4;
        const float* fb = feat + (size_t)b * NN * CC;
        #pragma unroll 8
        for (int i = 0; i < 32; i++) {
            const int n = nv + 32 * i;
            __half h = __float2half(fb[(size_t)n * CC + c]);
            sft[c][n] = __half_as_ushort(h);
        }
    }
    // ---- stage ev (f16 copy, 16B per thread) ----
    {
        const int r  = t >> 7;
        const int i8 = (t & 127) * 8;
        *(uint4*)&sev[r][i8] =
            *(const uint4*)(g_ev + (size_t)(b * HW + gv0 + r) * NN + i8);
    }
    __syncthreads();   // the only block barrier

    const int mt = wid & 7;
    const int rp = wid >> 3;
    const int r0 = lane >> 2;          // a-frag row within tile
    const int c0 = (lane & 3) * 2;     // a-frag k-pair base

    const unsigned short* euA_p =
        g_euT + ((size_t)(b * HW) + mt * 16 + r0) * NN;   // gu_a row
    const unsigned short* euB_p = euA_p + 8 * NN;          // gu_b = gu_a + 8

    float acc[2][2][4];
    #pragma unroll
    for (int rr = 0; rr < 2; rr++)
        #pragma unroll
        for (int nt = 0; nt < 2; nt++)
            #pragma unroll
            for (int q = 0; q < 4; q++) acc[rr][nt][q] = 0.0f;

    uint32_t euc[16], eun[16];
    // euc layout per ks: [0]=gu_a@nA [1]=gu_a@nB [2]=gu_b@nA [3]=gu_b@nB
#define LOAD_EU(arr, base)                                                   \
    do {                                                                     \
        _Pragma("unroll")                                                    \
        for (int ks_ = 0; ks_ < 4; ks_++) {                                  \
            const int na_ = (base) + ks_ * 16 + c0;                          \
            (arr)[ks_ * 4 + 0] = *(const uint32_t*)(euA_p + na_);            \
            (arr)[ks_ * 4 + 1] = *(const uint32_t*)(euA_p + na_ + 8);        \
            (arr)[ks_ * 4 + 2] = *(const uint32_t*)(euB_p + na_);            \
            (arr)[ks_ * 4 + 3] = *(const uint32_t*)(euB_p + na_ + 8);        \
        }                                                                    \
    } while (0)

    LOAD_EU(euc, 0);

    #pragma unroll 1
    for (int k = 0; k < 16; k++) {
        const int nb = k * 64;
        if (k < 15) LOAD_EU(eun, nb + 64);

        #pragma unroll
        for (int ks = 0; ks < 4; ks++) {
            const int nA = nb + ks * 16 + c0;
            const int nB = nA + 8;

            // ev pairs for both gv rows (smem, broadcast across lane quads)
            const uint32_t e0A = *(const uint32_t*)&sev[rp * 2][nA];
            const uint32_t e0B = *(const uint32_t*)&sev[rp * 2][nB];
            const uint32_t e1A = *(const uint32_t*)&sev[rp * 2 + 1][nA];
            const uint32_t e1B = *(const uint32_t*)&sev[rp * 2 + 1][nB];

            // B fragments (featT smem, conflict-free)
            uint32_t b0[2] = { *(const uint32_t*)&sft[r0][nA],
                               *(const uint32_t*)&sft[r0][nB] };
            uint32_t b1[2] = { *(const uint32_t*)&sft[r0 + 8][nA],
                               *(const uint32_t*)&sft[r0 + 8][nB] };

            // A fragments = ev * eu, directly in mma layout
            uint32_t a0[4] = { hmul2(e0A, euc[ks * 4 + 0]),
                               hmul2(e0A, euc[ks * 4 + 2]),
                               hmul2(e0B, euc[ks * 4 + 1]),
                               hmul2(e0B, euc[ks * 4 + 3]) };
            mma16816(acc[0][0], a0, b0);
            mma16816(acc[0][1], a0, b1);

            uint32_t a1[4] = { hmul2(e1A, euc[ks * 4 + 0]),
                               hmul2(e1A, euc[ks * 4 + 2]),
                               hmul2(e1B, euc[ks * 4 + 1]),
                               hmul2(e1B, euc[ks * 4 + 3]) };
            mma16816(acc[1][0], a1, b0);
            mma16816(acc[1][1], a1, b1);
        }
        #pragma unroll
        for (int q = 0; q < 16; q++) euc[q] = eun[q];
    }

    // ---- epilogue: D[gu][c] -> out[b][c][gv][gu] ----
    {
        const int guw = mt * 16 + (lane >> 2);
        const int c0w = (lane & 3) * 2;
        #pragma unroll
        for (int rr = 0; rr < 2; rr++) {
            const int gv = gv0 + rp * 2 + rr;
            float* ob = out + (size_t)b * CC * HW * HW + (size_t)gv * HW;
            #pragma unroll
            for (int nt = 0; nt < 2; nt++) {
                const int c = nt * 8 + c0w;
                ob[(size_t)c * HW * HW + guw]           = acc[rr][nt][0];
                ob[(size_t)(c + 1) * HW * HW + guw]     = acc[rr][nt][1];
                ob[(size_t)c * HW * HW + guw + 8]       = acc[rr][nt][2];
                ob[(size_t)(c + 1) * HW * HW + guw + 8] = acc[rr][nt][3];
            }
        }
    }
}

extern "C" void kernel_launch(void* const* d_in, const int* in_sizes, int n_in,
                              void* d_out, int out_size)
{
    const float* Kc    = (const float*)d_in[0];
    const float* RT    = (const float*)d_in[1];
    const float* pts3d = (const float*)d_in[2];
    const float* feat  = (const float*)d_in[3];
    const float* scale = (const float*)d_in[4];
    float* out = (float*)d_out;

    proj_kernel<<<BB * NN / 32, 128>>>(Kc, RT, pts3d, scale);
    accum_kernel<<<BB * 32, 512>>>(feat, out);
}

// round 8
// speedup vs baseline: 1.5008x; 1.5008x over previous
#include <cuda_runtime.h>
#include <cuda_fp16.h>
#include <cstdint>

// Problem constants: B=4, N=1024, C=16, H=W=128
#define BB 4
#define NN 1024
#define CC 16
#define HW 128

// f16 separable factors: ev [b][gv][n], euT [b][gu][n] (gu-major)
__device__ unsigned short g_ev [BB * HW * NN];
__device__ unsigned short g_euT[BB * HW * NN];

__device__ __forceinline__ float ex2f(float x) {
    float y;
    asm("ex2.approx.ftz.f32 %0, %1;" : "=f"(y) : "f"(x));
    return y;
}

__device__ __forceinline__ uint32_t hmul2(uint32_t a, uint32_t b) {
    uint32_t d;
    asm("mul.rn.f16x2 %0, %1, %2;" : "=r"(d) : "r"(a), "r"(b));
    return d;
}

__device__ __forceinline__ void mma16816(float* d, const uint32_t* a,
                                         const uint32_t* b) {
    asm volatile(
        "mma.sync.aligned.m16n8k16.row.col.f32.f16.f16.f32 "
        "{%0,%1,%2,%3}, {%4,%5,%6,%7}, {%8,%9}, {%0,%1,%2,%3};"
        : "+f"(d[0]), "+f"(d[1]), "+f"(d[2]), "+f"(d[3])
        : "r"(a[0]), "r"(a[1]), "r"(a[2]), "r"(a[3]), "r"(b[0]), "r"(b[1]));
}

// ---------------------------------------------------------------------------
// Kernel A: project points, write f16 separable factors (unchanged from R7).
// ---------------------------------------------------------------------------
__global__ void __launch_bounds__(128) proj_kernel(
    const float* __restrict__ Kc,
    const float* __restrict__ RT,
    const float* __restrict__ pts3d,
    const float* __restrict__ scale)
{
    const int b  = blockIdx.x >> 5;
    const int n0 = (blockIdx.x & 31) << 5;
    const int tid = threadIdx.x;

    __shared__ float su[32], sv[32], sinv[32], smask[32];

    if (tid < 32) {
        const int n = n0 + tid;
        const float* rt = RT + b * 12;
        const float* p  = pts3d + (b * NN + n) * 3;
        float p0 = p[0], p1 = p[1], p2 = p[2];
        float l0 = rt[0] * p0 + rt[1] * p1 + rt[2]  * p2 + rt[3];
        float l1 = rt[4] * p0 + rt[5] * p1 + rt[6]  * p2 + rt[7];
        float l2 = rt[8] * p0 + rt[9] * p1 + rt[10] * p2 + rt[11];
        float x = Kc[0] * l0 + Kc[1] * l1 + Kc[2] * l2;
        float y = Kc[3] * l0 + Kc[4] * l1 + Kc[5] * l2;
        float z = Kc[6] * l0 + Kc[7] * l1 + Kc[8] * l2;
        float mask = (z > 0.1f) ? 1.0f : 0.0f;
        float zc = fmaxf(z, 0.1f);
        float sig = Kc[0] * 0.03125f;            // sigma = K[0,0]/32
        float inv = 1.0f / (scale[b * NN + n] * sig * sig);
        su[tid]   = x / zc;
        sv[tid]   = y / zc;
        sinv[tid] = -1.4426950408889634f * inv;  // fold -log2(e)
        smask[tid] = mask;
    }
    __syncthreads();

    const int warp = tid >> 5;
    const int lane = tid & 31;

    {
        const float v  = sv[lane];
        const float ni = sinv[lane];
        unsigned short* dst = g_ev + (size_t)(b * HW) * NN + n0 + lane;
        #pragma unroll 8
        for (int j = 0; j < 32; j++) {
            const int gv = warp * 32 + j;
            float d = v - (float)gv;
            __half h = __float2half(ex2f(d * d * ni));
            dst[(size_t)gv * NN] = __half_as_ushort(h);
        }
    }
    {
        const int i = lane;
        const float u  = su[i];
        const float ni = sinv[i];
        const float m  = smask[i];
        unsigned short* dst = g_euT + (size_t)(b * HW) * NN + n0 + i;
        #pragma unroll 8
        for (int j = 0; j < 32; j++) {
            const int gu = warp * 32 + j;
            float d = u - (float)gu;
            __half h = __float2half(ex2f(d * d * ni) * m);
            dst[(size_t)gu * NN] = __half_as_ushort(h);
        }
    }
}

// ---------------------------------------------------------------------------
// Kernel B: register-direct HMMA GEMM with coalesced, double-buffered eu tile.
// grid = 128 CTAs = (b, 4 gv rows), 512 threads = 16 warps.
// Per chunk (64 n): stage euT[128 gu][64 n] via coalesced LDG.128 into padded
// smem (row stride 72 halfwords -> conflict-free quad-pattern LDS), consume
// with register-built A fragments:  a = f16x2( ev[r] * euT[gu] ).
// ---------------------------------------------------------------------------
#define EU_STRIDE 72                       // halfwords per padded eu row
#define SEU_OFF   0u                       // 2 x 128 x 72 x 2B = 36864
#define SFT_OFF   36864u                   // 16 x 1032 x 2B   = 33024
#define SEV_OFF   69888u                   // 4 x 1024 x 2B    =  8192
#define SMEM_DYN  78592u

__global__ void __launch_bounds__(512, 1) accum_kernel(
    const float* __restrict__ feat,
    float* __restrict__ out)
{
    extern __shared__ __align__(16) char smem[];
    unsigned short* seu = (unsigned short*)(smem + SEU_OFF);  // [2][128][72]
    unsigned short* sft = (unsigned short*)(smem + SFT_OFF);  // [16][1032]
    unsigned short* sev = (unsigned short*)(smem + SEV_OFF);  // [4][1024]

    const int b   = blockIdx.x >> 5;
    const int gv0 = (blockIdx.x & 31) << 2;
    const int t    = threadIdx.x;
    const int wid  = t >> 5;
    const int lane = t & 31;

    // ---- stage featT (f32 -> f16), padded stride 1032 ----
    {
        const int c  = t & 15;
        const int nv = t >> 4;
        const float* fb = feat + (size_t)b * NN * CC;
        #pragma unroll 8
        for (int i = 0; i < 32; i++) {
            const int n = nv + 32 * i;
            sft[c * 1032 + n] =
                __half_as_ushort(__float2half(fb[(size_t)n * CC + c]));
        }
    }
    // ---- stage ev rows (f16 copy, 16B/thread) ----
    {
        const int r  = t >> 7;
        const int i8 = (t & 127) * 8;
        *(uint4*)&sev[r * 1024 + i8] =
            *(const uint4*)(g_ev + (size_t)(b * HW + gv0 + r) * NN + i8);
    }

    // eu staging mapping: 4 threads per gu row, 16 halfwords (32B) each
    const int srow = t >> 2;
    const int sq   = (t & 3) * 16;
    const unsigned short* esrc = g_euT + (size_t)(b * HW + srow) * NN + sq;
    unsigned short* edst = seu + srow * EU_STRIDE + sq;

    // stage chunk 0 into buffer 0
    {
        const uint4 p0 = *(const uint4*)esrc;
        const uint4 p1 = *(const uint4*)(esrc + 8);
        *(uint4*)edst       = p0;
        *(uint4*)(edst + 8) = p1;
    }
    __syncthreads();

    // consumer mapping
    const int mt = wid & 7;
    const int rp = wid >> 3;
    const int r0 = lane >> 2;
    const int c0 = (lane & 3) * 2;

    const unsigned short* evr0 = sev + (rp * 2) * 1024;
    const unsigned short* evr1 = evr0 + 1024;
    const unsigned short* ftA  = sft + r0 * 1032;
    const unsigned short* ftB  = ftA + 8 * 1032;
    const int rowA = (mt * 16 + r0) * EU_STRIDE + c0;
    const int rowB = rowA + 8 * EU_STRIDE;

    float acc[2][2][4];
    #pragma unroll
    for (int rr = 0; rr < 2; rr++)
        #pragma unroll
        for (int nt = 0; nt < 2; nt++)
            #pragma unroll
            for (int q = 0; q < 4; q++) acc[rr][nt][q] = 0.0f;

    #pragma unroll 1
    for (int k = 0; k < 16; k++) {
        const int nb = k * 64;
        // prefetch next eu chunk into registers (coalesced LDG.128)
        uint4 p0, p1;
        if (k < 15) {
            const unsigned short* s = esrc + (size_t)(nb + 64);
            p0 = *(const uint4*)s;
            p1 = *(const uint4*)(s + 8);
        }

        const unsigned short* eub = seu + (k & 1) * (128 * EU_STRIDE);
        #pragma unroll
        for (int ks = 0; ks < 4; ks++) {
            const int nA = nb + ks * 16 + c0;
            const int nB = nA + 8;
            const int sA = ks * 16;          // within-chunk offset

            const uint32_t e0A = *(const uint32_t*)(evr0 + nA);
            const uint32_t e0B = *(const uint32_t*)(evr0 + nB);
            const uint32_t e1A = *(const uint32_t*)(evr1 + nA);
            const uint32_t e1B = *(const uint32_t*)(evr1 + nB);

            uint32_t bf0[2] = { *(const uint32_t*)(ftA + nA),
                                *(const uint32_t*)(ftA + nB) };
            uint32_t bf1[2] = { *(const uint32_t*)(ftB + nA),
                                *(const uint32_t*)(ftB + nB) };

            const uint32_t uAa = *(const uint32_t*)(eub + rowA + sA);
            const uint32_t uAb = *(const uint32_t*)(eub + rowA + sA + 8);
            const uint32_t uBa = *(const uint32_t*)(eub + rowB + sA);
            const uint32_t uBb = *(const uint32_t*)(eub + rowB + sA + 8);

            uint32_t a0[4] = { hmul2(e0A, uAa), hmul2(e0A, uBa),
                               hmul2(e0B, uAb), hmul2(e0B, uBb) };
            mma16816(acc[0][0], a0, bf0);
            mma16816(acc[0][1], a0, bf1);

            uint32_t a1[4] = { hmul2(e1A, uAa), hmul2(e1A, uBa),
                               hmul2(e1B, uAb), hmul2(e1B, uBb) };
            mma16816(acc[1][0], a1, bf0);
            mma16816(acc[1][1], a1, bf1);
        }

        if (k < 15) {
            unsigned short* d = edst + ((k + 1) & 1) * (128 * EU_STRIDE);
            *(uint4*)d       = p0;
            *(uint4*)(d + 8) = p1;
        }
        __syncthreads();
    }

    // ---- epilogue: D[gu][c] -> out[b][c][gv][gu] ----
    {
        const int guw = mt * 16 + (lane >> 2);
        const int c0w = (lane & 3) * 2;
        #pragma unroll
        for (int rr = 0; rr < 2; rr++) {
            const int gv = gv0 + rp * 2 + rr;
            float* ob = out + (size_t)b * CC * HW * HW + (size_t)gv * HW;
            #pragma unroll
            for (int nt = 0; nt < 2; nt++) {
                const int c = nt * 8 + c0w;
                ob[(size_t)c * HW * HW + guw]           = acc[rr][nt][0];
                ob[(size_t)(c + 1) * HW * HW + guw]     = acc[rr][nt][1];
                ob[(size_t)c * HW * HW + guw + 8]       = acc[rr][nt][2];
                ob[(size_t)(c + 1) * HW * HW + guw + 8] = acc[rr][nt][3];
            }
        }
    }
}

extern "C" void kernel_launch(void* const* d_in, const int* in_sizes, int n_in,
                              void* d_out, int out_size)
{
    const float* Kc    = (const float*)d_in[0];
    const float* RT    = (const float*)d_in[1];
    const float* pts3d = (const float*)d_in[2];
    const float* feat  = (const float*)d_in[3];
    const float* scale = (const float*)d_in[4];
    float* out = (float*)d_out;

    cudaFuncSetAttribute(accum_kernel,
                         cudaFuncAttributeMaxDynamicSharedMemorySize, SMEM_DYN);

    proj_kernel<<<BB * NN / 32, 128>>>(Kc, RT, pts3d, scale);
    accum_kernel<<<BB * 32, 512, SMEM_DYN>>>(feat, out);
}